// round 3
// baseline (speedup 1.0000x reference)
#include <cuda_runtime.h>
#include <cstdint>

// ---------------------------------------------------------------------------
// PrunedGroupSum: y[b,g] = (sum over contiguous column group g of x[b,:]) / 20
//   x:           [B, D] float32   (B=1024, D=262144 -> 1 GiB, streaming)
//   group_sizes: [K]    int32     (K=1000, sums to D)
//   out:         [B, K] float32
//
// R3: warp = (group, 4 rows); column loop unrolled x2 -> 8 independent
// LDG.128 per loop body (4KB in flight per warp-iteration). No atomics.
// ---------------------------------------------------------------------------

#define MAX_K 4096
__device__ int g_offsets[MAX_K + 1];

// 1-block Hillis-Steele inclusive scan of group_sizes (K <= 1024; K=1000 here).
__global__ void pgs_scan_kernel(const int* __restrict__ gs, int K) {
    __shared__ int sh[1024];
    int t = threadIdx.x;
    int v = (t < K) ? gs[t] : 0;
    sh[t] = v;
    __syncthreads();
#pragma unroll
    for (int off = 1; off < 1024; off <<= 1) {
        int add = (t >= off) ? sh[t - off] : 0;
        __syncthreads();
        sh[t] += add;
        __syncthreads();
    }
    if (t == 0) g_offsets[0] = 0;
    if (t < K) g_offsets[t + 1] = sh[t];
}

__device__ __forceinline__ float hsum4(float4 v) {
    return (v.x + v.y) + (v.z + v.w);
}

__global__ __launch_bounds__(256) void pgs_sum4u2_kernel(
    const float* __restrict__ x,
    float* __restrict__ out,
    int D, int K, int B)
{
    int g = blockIdx.x * 8 + (threadIdx.x >> 5);
    if (g >= K) return;
    int lane = threadIdx.x & 31;
    int row0 = blockIdx.y << 2;
    int nrows = B - row0;
    if (nrows > 4) nrows = 4;

    int s = g_offsets[g];
    int e = g_offsets[g + 1];

    const float* p0 = x + (size_t)row0 * (size_t)D;
    const float* p1 = p0 + D;
    const float* p2 = p1 + D;
    const float* p3 = p2 + D;

    float a0 = 0.f, a1 = 0.f, a2 = 0.f, a3 = 0.f;

    int s4 = (s + 3) & ~3;
    int e4 = e & ~3;

    if (nrows == 4) {
        if (s4 >= e4) {
            for (int c = s + lane; c < e; c += 32) {
                a0 += __ldcs(p0 + c);
                a1 += __ldcs(p1 + c);
                a2 += __ldcs(p2 + c);
                a3 += __ldcs(p3 + c);
            }
        } else {
            // head (<=3 scalar cols)
            {
                int c = s + lane;
                if (c < s4) {
                    a0 += __ldcs(p0 + c);
                    a1 += __ldcs(p1 + c);
                    a2 += __ldcs(p2 + c);
                    a3 += __ldcs(p3 + c);
                }
            }
            int c4 = s4 + lane * 4;
            // unroll-2 main: 8 independent LDG.128 issued back-to-back
            for (; c4 + 128 < e4; c4 += 256) {
                float4 v0 = __ldcs(reinterpret_cast<const float4*>(p0 + c4));
                float4 v1 = __ldcs(reinterpret_cast<const float4*>(p1 + c4));
                float4 v2 = __ldcs(reinterpret_cast<const float4*>(p2 + c4));
                float4 v3 = __ldcs(reinterpret_cast<const float4*>(p3 + c4));
                float4 w0 = __ldcs(reinterpret_cast<const float4*>(p0 + c4 + 128));
                float4 w1 = __ldcs(reinterpret_cast<const float4*>(p1 + c4 + 128));
                float4 w2 = __ldcs(reinterpret_cast<const float4*>(p2 + c4 + 128));
                float4 w3 = __ldcs(reinterpret_cast<const float4*>(p3 + c4 + 128));
                a0 += hsum4(v0) + hsum4(w0);
                a1 += hsum4(v1) + hsum4(w1);
                a2 += hsum4(v2) + hsum4(w2);
                a3 += hsum4(v3) + hsum4(w3);
            }
            // remainder vector tile (0 or 1 per lane)
            if (c4 < e4) {
                float4 v0 = __ldcs(reinterpret_cast<const float4*>(p0 + c4));
                float4 v1 = __ldcs(reinterpret_cast<const float4*>(p1 + c4));
                float4 v2 = __ldcs(reinterpret_cast<const float4*>(p2 + c4));
                float4 v3 = __ldcs(reinterpret_cast<const float4*>(p3 + c4));
                a0 += hsum4(v0);
                a1 += hsum4(v1);
                a2 += hsum4(v2);
                a3 += hsum4(v3);
            }
            // tail (<=3 scalar cols)
            {
                int c = e4 + lane;
                if (c < e) {
                    a0 += __ldcs(p0 + c);
                    a1 += __ldcs(p1 + c);
                    a2 += __ldcs(p2 + c);
                    a3 += __ldcs(p3 + c);
                }
            }
        }
    } else {
        for (int r = 0; r < nrows; r++) {
            const float* p = x + (size_t)(row0 + r) * (size_t)D;
            float a = 0.f;
            for (int c = s + lane; c < e; c += 32) a += __ldcs(p + c);
            if (r == 0) a0 = a; else if (r == 1) a1 = a;
            else if (r == 2) a2 = a; else a3 = a;
        }
    }

#pragma unroll
    for (int o = 16; o > 0; o >>= 1) {
        a0 += __shfl_xor_sync(0xffffffffu, a0, o);
        a1 += __shfl_xor_sync(0xffffffffu, a1, o);
        a2 += __shfl_xor_sync(0xffffffffu, a2, o);
        a3 += __shfl_xor_sync(0xffffffffu, a3, o);
    }

    if (lane == 0) {
        const float inv_tau = 1.0f / 20.0f;
        size_t ob = (size_t)row0 * (size_t)K + g;
        out[ob] = a0 * inv_tau;
        if (nrows > 1) out[ob + K] = a1 * inv_tau;
        if (nrows > 2) out[ob + 2 * (size_t)K] = a2 * inv_tau;
        if (nrows > 3) out[ob + 3 * (size_t)K] = a3 * inv_tau;
    }
}

extern "C" void kernel_launch(void* const* d_in, const int* in_sizes, int n_in,
                              void* d_out, int out_size) {
    const float* x  = (const float*)d_in[0];
    const int*   gs = (const int*)d_in[1];

    int K = in_sizes[1];
    int B = out_size / K;
    int D = in_sizes[0] / B;

    float* out = (float*)d_out;

    pgs_scan_kernel<<<1, 1024>>>(gs, K);

    dim3 grid((K + 7) / 8, (B + 3) / 4);
    pgs_sum4u2_kernel<<<grid, 256>>>(x, out, D, K, B);
}

// round 4
// speedup vs baseline: 1.1027x; 1.1027x over previous
#include <cuda_runtime.h>
#include <cstdint>

// ---------------------------------------------------------------------------
// PrunedGroupSum: y[b,g] = (sum over contiguous column group g of x[b,:]) / 20
//   x:           [B, D] float32   (B=1024, D=262144 -> 1 GiB, streaming)
//   group_sizes: [K]    int32     (K=1000, sums to D)
//   out:         [B, K] float32
//
// R4: warp = (group, 8 rows) -> 8 independent LDG.128 per loop iteration,
// __launch_bounds__(128, 6) lifts the register ceiling (~85) so ptxas keeps
// all 8 loads in flight (R2/R3 were reg-capped at 40 -> serialized loads).
// ---------------------------------------------------------------------------

#define MAX_K 4096
#define ROWS_PER_WARP 8

__device__ int g_offsets[MAX_K + 1];

// 1-block Hillis-Steele inclusive scan of group_sizes (K <= 1024; K=1000 here).
__global__ void pgs_scan_kernel(const int* __restrict__ gs, int K) {
    __shared__ int sh[1024];
    int t = threadIdx.x;
    int v = (t < K) ? gs[t] : 0;
    sh[t] = v;
    __syncthreads();
#pragma unroll
    for (int off = 1; off < 1024; off <<= 1) {
        int add = (t >= off) ? sh[t - off] : 0;
        __syncthreads();
        sh[t] += add;
        __syncthreads();
    }
    if (t == 0) g_offsets[0] = 0;
    if (t < K) g_offsets[t + 1] = sh[t];
}

__device__ __forceinline__ float hsum4(float4 v) {
    return (v.x + v.y) + (v.z + v.w);
}

__global__ __launch_bounds__(128, 6) void pgs_sum8_kernel(
    const float* __restrict__ x,
    float* __restrict__ out,
    int D, int K, int B)
{
    int g = blockIdx.x * 4 + (threadIdx.x >> 5);
    if (g >= K) return;
    int lane = threadIdx.x & 31;
    int row0 = blockIdx.y * ROWS_PER_WARP;
    int nrows = B - row0;
    if (nrows > ROWS_PER_WARP) nrows = ROWS_PER_WARP;

    int s = g_offsets[g];
    int e = g_offsets[g + 1];

    const float* p = x + (size_t)row0 * (size_t)D;
    const size_t SD = (size_t)D;

    float acc[ROWS_PER_WARP];
#pragma unroll
    for (int r = 0; r < ROWS_PER_WARP; r++) acc[r] = 0.0f;

    int s4 = (s + 3) & ~3;
    int e4 = e & ~3;

    if (nrows == ROWS_PER_WARP) {
        if (s4 >= e4) {
            // tiny group: scalar, coalesced across lanes, 8 streams
            for (int c = s + lane; c < e; c += 32) {
#pragma unroll
                for (int r = 0; r < ROWS_PER_WARP; r++)
                    acc[r] += __ldcs(p + (size_t)r * SD + c);
            }
        } else {
            // head (<=3 scalar cols)
            {
                int c = s + lane;
                if (c < s4) {
#pragma unroll
                    for (int r = 0; r < ROWS_PER_WARP; r++)
                        acc[r] += __ldcs(p + (size_t)r * SD + c);
                }
            }
            // main: 8 independent LDG.128 staged before any accumulation
            for (int c4 = s4 + lane * 4; c4 < e4; c4 += 128) {
                float4 v[ROWS_PER_WARP];
#pragma unroll
                for (int r = 0; r < ROWS_PER_WARP; r++)
                    v[r] = __ldcs(reinterpret_cast<const float4*>(p + (size_t)r * SD + c4));
#pragma unroll
                for (int r = 0; r < ROWS_PER_WARP; r++)
                    acc[r] += hsum4(v[r]);
            }
            // tail (<=3 scalar cols)
            {
                int c = e4 + lane;
                if (c < e) {
#pragma unroll
                    for (int r = 0; r < ROWS_PER_WARP; r++)
                        acc[r] += __ldcs(p + (size_t)r * SD + c);
                }
            }
        }
    } else {
        // remainder rows: simple per-row scalar path
        for (int r = 0; r < nrows; r++) {
            const float* pr = p + (size_t)r * SD;
            float a = 0.f;
            for (int c = s + lane; c < e; c += 32) a += __ldcs(pr + c);
            acc[r] = a;
        }
    }

    // butterfly reduce all 8 accumulators
#pragma unroll
    for (int r = 0; r < ROWS_PER_WARP; r++) {
#pragma unroll
        for (int o = 16; o > 0; o >>= 1)
            acc[r] += __shfl_xor_sync(0xffffffffu, acc[r], o);
    }

    if (lane == 0) {
        const float inv_tau = 1.0f / 20.0f;
        size_t ob = (size_t)row0 * (size_t)K + g;
#pragma unroll
        for (int r = 0; r < ROWS_PER_WARP; r++)
            if (r < nrows) out[ob + (size_t)r * (size_t)K] = acc[r] * inv_tau;
    }
}

extern "C" void kernel_launch(void* const* d_in, const int* in_sizes, int n_in,
                              void* d_out, int out_size) {
    const float* x  = (const float*)d_in[0];
    const int*   gs = (const int*)d_in[1];

    int K = in_sizes[1];
    int B = out_size / K;
    int D = in_sizes[0] / B;

    float* out = (float*)d_out;

    pgs_scan_kernel<<<1, 1024>>>(gs, K);

    dim3 grid((K + 3) / 4, (B + ROWS_PER_WARP - 1) / ROWS_PER_WARP);
    pgs_sum8_kernel<<<grid, 128>>>(x, out, D, K, B);
}